// round 3
// baseline (speedup 1.0000x reference)
#include <cuda_runtime.h>

// Problem constants (fixed by the reference):
//   feature [B=2048, F=128, E=64] fp32
//   Q,K,V   [H=4, E=64, A=64]     fp32
//   res_w   [E=64, H*A=256]       fp32
//   out     [B=2048, F=128, 256]  fp32 = relu(attn + feature@res_w)
//
// Strategy: one CTA per (b,h). All tensors for that tile live in shared
// memory; all GEMMs are register-tiled fp32 FFMA (full accuracy; the
// un-scaled logits have std~16 so low-precision tensor paths are unsafe
// without hi/lo splitting — planned for a later round).

#define B_ 2048
#define F_ 128
#define E_ 64
#define H_ 4
#define A_ 64

#define LDF 68    // padded row stride (floats) for 128x64 tiles: 68%32=4 -> conflict-friendly, 16B aligned
#define LDW 68    // stride for staged 64x64 weight tile
#define LDSS 132  // stride for 128x128 score matrix

// Shared memory plan (floats):
//   sf   : F_*LDF   = 8704
//   sq   : F_*LDF   = 8704
//   sk   : F_*LDF   = 8704
//   sv   : F_*LDF   = 8704
//   sS   : F_*LDSS  = 16896   (first 64*LDW floats double as weight staging)
//   ssum : F_       = 128
// total = 51840 floats = 207360 bytes  (< 227KB dynamic smem limit)
#define SMEM_FLOATS (4 * F_ * LDF + F_ * LDSS + F_)
#define SMEM_BYTES (SMEM_FLOATS * 4)

__global__ __launch_bounds__(256, 1)
void attn_ffn_kernel(const float* __restrict__ feature,
                     const float* __restrict__ Qw,
                     const float* __restrict__ Kw,
                     const float* __restrict__ Vw,
                     const float* __restrict__ res_w,
                     float* __restrict__ out) {
    extern __shared__ float smem[];
    const int b = blockIdx.x >> 2;   // blockIdx.x = b*H + h
    const int h = blockIdx.x & 3;
    const int t = threadIdx.x;

    float* sf = smem;
    float* sq = sf + F_ * LDF;
    float* sk = sq + F_ * LDF;
    float* sv = sk + F_ * LDF;
    float* sS = sv + F_ * LDF;       // also weight-staging area (64*LDW floats)
    float* ssum = sS + F_ * LDSS;

    // ---------------- Phase 1: load feature[b] -> sf (float4 coalesced) ----
    {
        const float4* fg = reinterpret_cast<const float4*>(
            feature + (size_t)b * (F_ * E_));
        #pragma unroll
        for (int i = t; i < F_ * E_ / 4; i += 256) {
            float4 v = fg[i];
            int row = i >> 4;            // 16 float4 per 64-float row
            int c4  = (i & 15) << 2;
            *reinterpret_cast<float4*>(&sf[row * LDF + c4]) = v;
        }
    }
    __syncthreads();

    // ---------------- Projection GEMMs: dst[128x64] = sf @ W[64x64] --------
    // Thread layout: tr = t/16 (16 row groups of 8 rows), tc = t%16 (4 cols)
    auto proj = [&](const float* __restrict__ Wg, int wstride, float* dst) {
        float* sw = sS;  // stage weight tile
        #pragma unroll
        for (int i = t; i < E_ * A_ / 4; i += 256) {
            int e  = i >> 4;
            int c4 = (i & 15) << 2;
            *reinterpret_cast<float4*>(&sw[e * LDW + c4]) =
                *reinterpret_cast<const float4*>(Wg + e * wstride + c4);
        }
        __syncthreads();

        const int tr = t >> 4, tc = t & 15;
        const int r0 = tr * 8, c0 = tc * 4;
        float acc[8][4] = {};
        #pragma unroll 4
        for (int e4 = 0; e4 < E_; e4 += 4) {
            float aa[8][4], bb[4][4];
            #pragma unroll
            for (int i = 0; i < 8; i++)
                *reinterpret_cast<float4*>(aa[i]) =
                    *reinterpret_cast<const float4*>(&sf[(r0 + i) * LDF + e4]);
            #pragma unroll
            for (int u = 0; u < 4; u++)
                *reinterpret_cast<float4*>(bb[u]) =
                    *reinterpret_cast<const float4*>(&sw[(e4 + u) * LDW + c0]);
            #pragma unroll
            for (int u = 0; u < 4; u++)
                #pragma unroll
                for (int i = 0; i < 8; i++)
                    #pragma unroll
                    for (int j = 0; j < 4; j++)
                        acc[i][j] = fmaf(aa[i][u], bb[u][j], acc[i][j]);
        }
        #pragma unroll
        for (int i = 0; i < 8; i++)
            *reinterpret_cast<float4*>(&dst[(r0 + i) * LDF + c0]) =
                *reinterpret_cast<float4*>(acc[i]);
        __syncthreads();
    };

    proj(Qw + h * (E_ * A_), A_, sq);
    proj(Kw + h * (E_ * A_), A_, sk);
    proj(Vw + h * (E_ * A_), A_, sv);

    // ---------------- Phase 2: S = q @ k^T  (128x128) ----------------------
    // 8x8 tile per thread: tr = t/16 (rows), tc = t%16 (8-col groups)
    {
        const int tr = t >> 4, tc = t & 15;
        const int r0 = tr * 8, g0 = tc * 8;
        float acc[8][8] = {};
        #pragma unroll 2
        for (int a4 = 0; a4 < A_; a4 += 4) {
            float qa[8][4], kb[8][4];
            #pragma unroll
            for (int i = 0; i < 8; i++)
                *reinterpret_cast<float4*>(qa[i]) =
                    *reinterpret_cast<const float4*>(&sq[(r0 + i) * LDF + a4]);
            #pragma unroll
            for (int j = 0; j < 8; j++)
                *reinterpret_cast<float4*>(kb[j]) =
                    *reinterpret_cast<const float4*>(&sk[(g0 + j) * LDF + a4]);
            #pragma unroll
            for (int u = 0; u < 4; u++)
                #pragma unroll
                for (int i = 0; i < 8; i++)
                    #pragma unroll
                    for (int j = 0; j < 8; j++)
                        acc[i][j] = fmaf(qa[i][u], kb[j][u], acc[i][j]);
        }
        #pragma unroll
        for (int i = 0; i < 8; i++) {
            *reinterpret_cast<float4*>(&sS[(r0 + i) * LDSS + g0]) =
                *reinterpret_cast<float4*>(&acc[i][0]);
            *reinterpret_cast<float4*>(&sS[(r0 + i) * LDSS + g0 + 4]) =
                *reinterpret_cast<float4*>(&acc[i][4]);
        }
    }
    __syncthreads();

    // ---------------- Phase 3: row softmax (unnormalized; 1/sum in ssum) ---
    // 2 threads per row; lane pair (t, t^1) covers halves of one row.
    {
        const int row = t >> 1, half = t & 1;
        float* p = &sS[row * LDSS + half * 64];
        float m = -3.402823466e38f;
        #pragma unroll 8
        for (int c = 0; c < 64; c++) m = fmaxf(m, p[c]);
        m = fmaxf(m, __shfl_xor_sync(0xFFFFFFFFu, m, 1));
        float s = 0.f;
        #pragma unroll 8
        for (int c = 0; c < 64; c++) {
            float e = __expf(p[c] - m);
            p[c] = e;
            s += e;
        }
        s += __shfl_xor_sync(0xFFFFFFFFu, s, 1);
        if (half == 0) ssum[row] = 1.0f / s;
    }
    __syncthreads();

    // ---------------- Phase 4: em = softmax(S) @ v; fuse res GEMM + relu ---
    {
        const int tr = t >> 4, tc = t & 15;
        const int r0 = tr * 8, c0 = tc * 4;

        float em[8][4] = {};
        #pragma unroll 2
        for (int g4 = 0; g4 < F_; g4 += 4) {
            float pv[8][4], vb[4][4];
            #pragma unroll
            for (int i = 0; i < 8; i++)
                *reinterpret_cast<float4*>(pv[i]) =
                    *reinterpret_cast<const float4*>(&sS[(r0 + i) * LDSS + g4]);
            #pragma unroll
            for (int u = 0; u < 4; u++)
                *reinterpret_cast<float4*>(vb[u]) =
                    *reinterpret_cast<const float4*>(&sv[(g4 + u) * LDF + c0]);
            #pragma unroll
            for (int u = 0; u < 4; u++)
                #pragma unroll
                for (int i = 0; i < 8; i++)
                    #pragma unroll
                    for (int j = 0; j < 4; j++)
                        em[i][j] = fmaf(pv[i][u], vb[u][j], em[i][j]);
        }
        #pragma unroll
        for (int i = 0; i < 8; i++) {
            float inv = ssum[r0 + i];
            #pragma unroll
            for (int j = 0; j < 4; j++) em[i][j] *= inv;
        }
        __syncthreads();   // S dead; reuse its space for res_w staging

        // stage res_w[:, h*64 : h*64+64]
        float* sw = sS;
        #pragma unroll
        for (int i = t; i < E_ * A_ / 4; i += 256) {
            int e  = i >> 4;
            int c4 = (i & 15) << 2;
            *reinterpret_cast<float4*>(&sw[e * LDW + c4]) =
                *reinterpret_cast<const float4*>(res_w + e * (H_ * A_) + h * A_ + c4);
        }
        __syncthreads();

        float racc[8][4] = {};
        #pragma unroll 4
        for (int e4 = 0; e4 < E_; e4 += 4) {
            float aa[8][4], bb[4][4];
            #pragma unroll
            for (int i = 0; i < 8; i++)
                *reinterpret_cast<float4*>(aa[i]) =
                    *reinterpret_cast<const float4*>(&sf[(r0 + i) * LDF + e4]);
            #pragma unroll
            for (int u = 0; u < 4; u++)
                *reinterpret_cast<float4*>(bb[u]) =
                    *reinterpret_cast<const float4*>(&sw[(e4 + u) * LDW + c0]);
            #pragma unroll
            for (int u = 0; u < 4; u++)
                #pragma unroll
                for (int i = 0; i < 8; i++)
                    #pragma unroll
                    for (int j = 0; j < 4; j++)
                        racc[i][j] = fmaf(aa[i][u], bb[u][j], racc[i][j]);
        }

        // epilogue: out[b][f][h*64 + c] = relu(em + res)
        #pragma unroll
        for (int i = 0; i < 8; i++) {
            float4 o;
            o.x = fmaxf(em[i][0] + racc[i][0], 0.f);
            o.y = fmaxf(em[i][1] + racc[i][1], 0.f);
            o.z = fmaxf(em[i][2] + racc[i][2], 0.f);
            o.w = fmaxf(em[i][3] + racc[i][3], 0.f);
            size_t off = ((size_t)b * F_ + (r0 + i)) * (H_ * A_) + h * A_ + c0;
            *reinterpret_cast<float4*>(out + off) = o;
        }
    }
}

extern "C" void kernel_launch(void* const* d_in, const int* in_sizes, int n_in,
                              void* d_out, int out_size) {
    const float* feature = (const float*)d_in[0];
    const float* Qw      = (const float*)d_in[1];
    const float* Kw      = (const float*)d_in[2];
    const float* Vw      = (const float*)d_in[3];
    const float* res_w   = (const float*)d_in[4];
    float* out = (float*)d_out;

    cudaFuncSetAttribute(attn_ffn_kernel,
                         cudaFuncAttributeMaxDynamicSharedMemorySize, SMEM_BYTES);
    attn_ffn_kernel<<<B_ * H_, 256, SMEM_BYTES>>>(feature, Qw, Kw, Vw, res_w, out);
}

// round 8
// speedup vs baseline: 4.7642x; 4.7642x over previous
#include <cuda_runtime.h>
#include <cuda_bf16.h>
#include <cstdint>

// AttentionLayer: B=2048, F=128, E=64, H=4, A=64
//   out[b,f,h*64+a] = relu( softmax(q k^T) v + (feature @ res_w)[:, h*64:] )
//
// mma.sync (baseline PTX, legal on plain sm_103 target) tensor-core kernel.
// All five GEMMs run as bf16 hi/lo 3-term emulated fp32:
//   A*B ~= Ah*Bh + Ah*Bl + Al*Bh   (fp32 accumulate)
// 1 CTA per (b,h), 256 threads (8 warps), warp w owns output rows [16w,16w+16).

#define B_ 2048
#define F_ 128
#define E_ 64
#define H_ 4
#define A_ 64

// ---------------- smem layout (bytes). bf16 tiles, row stride 72 el = 144 B;
// P tiles stride 136 el = 272 B. All offsets 16B-aligned.
#define SM_FH    0        // f hi   [128x64] stride 144
#define SM_FL    18432
#define SM_WQH   36864    // W tiles [64x64] stride 144 (row-major [e][a])
#define SM_WQL   46080
#define SM_WKH   55296
#define SM_WKL   64512
#define SM_WVH   73728
#define SM_WVL   82944
#define SM_RH    92160    // res_w slice [64x64]
#define SM_RL    101376
#define SM_QH    110592   // q [128x64]
#define SM_QL    129024
#define SM_KH    147456   // k [128x64]
#define SM_KL    165888
#define SM_VH    184320   // v [128x64]
#define SM_VL    202752
#define SM_SSUM  221184   // float[128]
#define SMEM_BYTES 221696
// P overlays dead q/k space after S is computed:
#define SM_PH    110592   // P [128x128] stride 272  (34816 B)
#define SM_PL    145408   //   ends at 180224 < SM_VH ✓

// ---------------- PTX helpers ----------------------------------------------
__device__ __forceinline__ uint32_t smem_u32(const void* p) {
    uint32_t a;
    asm("{ .reg .u64 t; cvta.to.shared.u64 t, %1; cvt.u32.u64 %0, t; }"
        : "=r"(a) : "l"(p));
    return a;
}
__device__ __forceinline__ void ldsm4(uint32_t addr, uint32_t r[4]) {
    asm volatile("ldmatrix.sync.aligned.m8n8.x4.shared.b16 {%0,%1,%2,%3}, [%4];"
                 : "=r"(r[0]), "=r"(r[1]), "=r"(r[2]), "=r"(r[3]) : "r"(addr));
}
__device__ __forceinline__ void ldsm4t(uint32_t addr, uint32_t r[4]) {
    asm volatile("ldmatrix.sync.aligned.m8n8.x4.trans.shared.b16 {%0,%1,%2,%3}, [%4];"
                 : "=r"(r[0]), "=r"(r[1]), "=r"(r[2]), "=r"(r[3]) : "r"(addr));
}
__device__ __forceinline__ void mma16816(float d[4], const uint32_t a[4],
                                         uint32_t b0, uint32_t b1) {
    asm volatile(
        "mma.sync.aligned.m16n8k16.row.col.f32.bf16.bf16.f32 "
        "{%0,%1,%2,%3}, {%4,%5,%6,%7}, {%8,%9}, {%0,%1,%2,%3};"
        : "+f"(d[0]), "+f"(d[1]), "+f"(d[2]), "+f"(d[3])
        : "r"(a[0]), "r"(a[1]), "r"(a[2]), "r"(a[3]), "r"(b0), "r"(b1));
}

__device__ __forceinline__ uint32_t pack2(__nv_bfloat16 a, __nv_bfloat16 b) {
    return (uint32_t)__bfloat16_as_ushort(a) | ((uint32_t)__bfloat16_as_ushort(b) << 16);
}
// hi/lo split of (a,b): returns packed hi pair, writes packed lo pair.
__device__ __forceinline__ uint32_t pack_hilo(float a, float b, uint32_t& lo) {
    __nv_bfloat16 ha = __float2bfloat16_rn(a);
    __nv_bfloat16 hb = __float2bfloat16_rn(b);
    __nv_bfloat16 la = __float2bfloat16_rn(a - __bfloat162float(ha));
    __nv_bfloat16 lb = __float2bfloat16_rn(b - __bfloat162float(hb));
    lo = pack2(la, lb);
    return pack2(ha, hb);
}

// C[r0..r0+16, 0..64) += Af[r0..,0..64) @ Bop, K=64, 3-term hi/lo.
// BTRANS=true : B stored row-major [K=64][N=64] (weights)     -> ldmatrix.trans
// BTRANS=false: B stored row-major [N][K] (i.e. B^T natural)  -> ldmatrix
template <bool BTRANS>
__device__ __forceinline__ void gemm_k64(
    uint32_t sb, int r0, int lr, int lm,
    uint32_t ah_off, uint32_t al_off,
    uint32_t bh_off, uint32_t bl_off,
    float acc[8][4])
{
    #pragma unroll
    for (int ks = 0; ks < 4; ks++) {
        uint32_t a_rel = (uint32_t)((r0 + lr + ((lm & 1) << 3)) * 144 +
                                    (ks << 5) + ((lm >> 1) << 4));
        uint32_t ah[4], al[4];
        ldsm4(sb + ah_off + a_rel, ah);
        ldsm4(sb + al_off + a_rel, al);
        #pragma unroll
        for (int p = 0; p < 4; p++) {
            uint32_t b_rel;
            uint32_t bh[4], bl[4];
            if (BTRANS) {
                b_rel = (uint32_t)(((ks << 4) + lr + ((lm & 1) << 3)) * 144 +
                                   (p << 5) + ((lm >> 1) << 4));
                ldsm4t(sb + bh_off + b_rel, bh);
                ldsm4t(sb + bl_off + b_rel, bl);
            } else {
                b_rel = (uint32_t)(((p << 4) + lr + ((lm >> 1) << 3)) * 144 +
                                   (ks << 5) + ((lm & 1) << 4));
                ldsm4(sb + bh_off + b_rel, bh);
                ldsm4(sb + bl_off + b_rel, bl);
            }
            mma16816(acc[2 * p],     ah, bh[0], bh[1]);
            mma16816(acc[2 * p + 1], ah, bh[2], bh[3]);
            mma16816(acc[2 * p],     ah, bl[0], bl[1]);
            mma16816(acc[2 * p + 1], ah, bl[2], bl[3]);
            mma16816(acc[2 * p],     al, bh[0], bh[1]);
            mma16816(acc[2 * p + 1], al, bh[2], bh[3]);
        }
    }
}

__global__ __launch_bounds__(256, 1)
void attn_mma_kernel(const float* __restrict__ feature,
                     const float* __restrict__ Qw,
                     const float* __restrict__ Kw,
                     const float* __restrict__ Vw,
                     const float* __restrict__ res_w,
                     float* __restrict__ out) {
    extern __shared__ char smem[];
    const uint32_t sb = smem_u32(smem);
    const int t = threadIdx.x;
    const int w = t >> 5, l = t & 31;
    const int grp = l >> 2, qt = l & 3;      // C-fragment coords
    const int lr = l & 7, lm = l >> 3;       // ldmatrix lane coords
    const int b = blockIdx.x >> 2, h = blockIdx.x & 3;
    const int r0 = w * 16;                   // warp's output row base

    float* ssum = (float*)(smem + SM_SSUM);

    // ================= Phase 0: gmem -> smem bf16 hi/lo ====================
    {
        const float4* fg = (const float4*)(feature + (size_t)b * (F_ * E_));
        #pragma unroll
        for (int it = 0; it < 8; it++) {
            int i = t + it * 256;
            float4 v = fg[i];
            int row = i >> 4, c4 = (i & 15) << 2;
            uint32_t lo0, lo1;
            uint32_t h0 = pack_hilo(v.x, v.y, lo0);
            uint32_t h1 = pack_hilo(v.z, v.w, lo1);
            uint32_t off = (uint32_t)(row * 144 + (c4 << 1));
            *(uint2*)(smem + SM_FH + off) = make_uint2(h0, h1);
            *(uint2*)(smem + SM_FL + off) = make_uint2(lo0, lo1);
        }
        const float* srcs[4] = {Qw + h * (E_ * A_), Kw + h * (E_ * A_),
                                Vw + h * (E_ * A_), res_w + h * A_};
        const int strd[4] = {A_, A_, A_, H_ * A_};
        const int dsth[4] = {SM_WQH, SM_WKH, SM_WVH, SM_RH};
        const int dstl[4] = {SM_WQL, SM_WKL, SM_WVL, SM_RL};
        #pragma unroll
        for (int p = 0; p < 4; p++) {
            const float* s = srcs[p];
            const int st = strd[p];
            #pragma unroll
            for (int it = 0; it < 4; it++) {
                int i = t + it * 256;
                int e = i >> 4, c4 = (i & 15) << 2;
                float4 v = *(const float4*)(s + e * st + c4);
                uint32_t lo0, lo1;
                uint32_t h0 = pack_hilo(v.x, v.y, lo0);
                uint32_t h1 = pack_hilo(v.z, v.w, lo1);
                uint32_t off = (uint32_t)(e * 144 + (c4 << 1));
                *(uint2*)(smem + dsth[p] + off) = make_uint2(h0, h1);
                *(uint2*)(smem + dstl[p] + off) = make_uint2(lo0, lo1);
            }
        }
    }
    __syncthreads();

    // ================= Phase 1: q,k,v projections ==========================
    // store helper: write C tile (16 rows x 64 cols) as bf16 hi/lo
    auto store_hilo = [&](float acc[8][4], int oh, int ol) {
        #pragma unroll
        for (int i = 0; i < 8; i++) {
            int cbyte = (((i << 3) + (qt << 1)) << 1);
            uint32_t lo;
            uint32_t hi = pack_hilo(acc[i][0], acc[i][1], lo);
            *(uint32_t*)(smem + oh + (r0 + grp) * 144 + cbyte) = hi;
            *(uint32_t*)(smem + ol + (r0 + grp) * 144 + cbyte) = lo;
            hi = pack_hilo(acc[i][2], acc[i][3], lo);
            *(uint32_t*)(smem + oh + (r0 + grp + 8) * 144 + cbyte) = hi;
            *(uint32_t*)(smem + ol + (r0 + grp + 8) * 144 + cbyte) = lo;
        }
    };
    {
        float acc[8][4] = {};
        gemm_k64<true>(sb, r0, lr, lm, SM_FH, SM_FL, SM_WQH, SM_WQL, acc);
        store_hilo(acc, SM_QH, SM_QL);
    }
    {
        float acc[8][4] = {};
        gemm_k64<true>(sb, r0, lr, lm, SM_FH, SM_FL, SM_WKH, SM_WKL, acc);
        store_hilo(acc, SM_KH, SM_KL);
    }
    {
        float acc[8][4] = {};
        gemm_k64<true>(sb, r0, lr, lm, SM_FH, SM_FL, SM_WVH, SM_WVL, acc);
        store_hilo(acc, SM_VH, SM_VL);
    }
    __syncthreads();

    // ================= Phase 2: S = q k^T (16 rows x 128 cols per warp) ====
    float sacc[16][4] = {};
    #pragma unroll
    for (int ks = 0; ks < 4; ks++) {
        uint32_t a_rel = (uint32_t)((r0 + lr + ((lm & 1) << 3)) * 144 +
                                    (ks << 5) + ((lm >> 1) << 4));
        uint32_t ah[4], al[4];
        ldsm4(sb + SM_QH + a_rel, ah);
        ldsm4(sb + SM_QL + a_rel, al);
        #pragma unroll
        for (int p = 0; p < 8; p++) {
            uint32_t b_rel = (uint32_t)(((p << 4) + lr + ((lm >> 1) << 3)) * 144 +
                                        (ks << 5) + ((lm & 1) << 4));
            uint32_t bh[4], bl[4];
            ldsm4(sb + SM_KH + b_rel, bh);
            ldsm4(sb + SM_KL + b_rel, bl);
            mma16816(sacc[2 * p],     ah, bh[0], bh[1]);
            mma16816(sacc[2 * p + 1], ah, bh[2], bh[3]);
            mma16816(sacc[2 * p],     ah, bl[0], bl[1]);
            mma16816(sacc[2 * p + 1], ah, bl[2], bl[3]);
            mma16816(sacc[2 * p],     al, bh[0], bh[1]);
            mma16816(sacc[2 * p + 1], al, bh[2], bh[3]);
        }
    }

    // ================= Phase 3: softmax (rows in registers) ================
    // lane holds rows (r0+grp) in [i][0..1] and (r0+grp+8) in [i][2..3].
    float invA, invB;
    {
        float mA = -3.402823466e38f, mB = -3.402823466e38f;
        #pragma unroll
        for (int i = 0; i < 16; i++) {
            mA = fmaxf(mA, fmaxf(sacc[i][0], sacc[i][1]));
            mB = fmaxf(mB, fmaxf(sacc[i][2], sacc[i][3]));
        }
        mA = fmaxf(mA, __shfl_xor_sync(0xFFFFFFFFu, mA, 1));
        mA = fmaxf(mA, __shfl_xor_sync(0xFFFFFFFFu, mA, 2));
        mB = fmaxf(mB, __shfl_xor_sync(0xFFFFFFFFu, mB, 1));
        mB = fmaxf(mB, __shfl_xor_sync(0xFFFFFFFFu, mB, 2));
        float sA = 0.f, sB = 0.f;
        #pragma unroll
        for (int i = 0; i < 16; i++) {
            sacc[i][0] = __expf(sacc[i][0] - mA);
            sacc[i][1] = __expf(sacc[i][1] - mA);
            sacc[i][2] = __expf(sacc[i][2] - mB);
            sacc[i][3] = __expf(sacc[i][3] - mB);
            sA += sacc[i][0] + sacc[i][1];
            sB += sacc[i][2] + sacc[i][3];
        }
        sA += __shfl_xor_sync(0xFFFFFFFFu, sA, 1);
        sA += __shfl_xor_sync(0xFFFFFFFFu, sA, 2);
        sB += __shfl_xor_sync(0xFFFFFFFFu, sB, 1);
        sB += __shfl_xor_sync(0xFFFFFFFFu, sB, 2);
        invA = 1.0f / sA;
        invB = 1.0f / sB;
    }
    __syncthreads();   // all warps done reading q/k before P overwrites them

    // store P (unnormalized) hi/lo, stride 272
    {
        #pragma unroll
        for (int i = 0; i < 16; i++) {
            int cbyte = (((i << 3) + (qt << 1)) << 1);
            uint32_t lo;
            uint32_t hi = pack_hilo(sacc[i][0], sacc[i][1], lo);
            *(uint32_t*)(smem + SM_PH + (r0 + grp) * 272 + cbyte) = hi;
            *(uint32_t*)(smem + SM_PL + (r0 + grp) * 272 + cbyte) = lo;
            hi = pack_hilo(sacc[i][2], sacc[i][3], lo);
            *(uint32_t*)(smem + SM_PH + (r0 + grp + 8) * 272 + cbyte) = hi;
            *(uint32_t*)(smem + SM_PL + (r0 + grp + 8) * 272 + cbyte) = lo;
        }
        if (qt == 0) {
            ssum[r0 + grp] = invA;
            ssum[r0 + grp + 8] = invB;
        }
    }
    __syncthreads();

    // ================= Phase 4: em = P @ v  (K=128) ========================
    float eacc[8][4] = {};
    #pragma unroll
    for (int ks = 0; ks < 8; ks++) {
        uint32_t a_rel = (uint32_t)((r0 + lr + ((lm & 1) << 3)) * 272 +
                                    (ks << 5) + ((lm >> 1) << 4));
        uint32_t ah[4], al[4];
        ldsm4(sb + SM_PH + a_rel, ah);
        ldsm4(sb + SM_PL + a_rel, al);
        #pragma unroll
        for (int p = 0; p < 4; p++) {
            uint32_t b_rel = (uint32_t)(((ks << 4) + lr + ((lm & 1) << 3)) * 144 +
                                        (p << 5) + ((lm >> 1) << 4));
            uint32_t bh[4], bl[4];
            ldsm4t(sb + SM_VH + b_rel, bh);
            ldsm4t(sb + SM_VL + b_rel, bl);
            mma16816(eacc[2 * p],     ah, bh[0], bh[1]);
            mma16816(eacc[2 * p + 1], ah, bh[2], bh[3]);
            mma16816(eacc[2 * p],     ah, bl[0], bl[1]);
            mma16816(eacc[2 * p + 1], ah, bl[2], bl[3]);
            mma16816(eacc[2 * p],     al, bh[0], bh[1]);
            mma16816(eacc[2 * p + 1], al, bh[2], bh[3]);
        }
    }

    // ================= Phase 5: res = f @ res_w slice ======================
    float racc[8][4] = {};
    gemm_k64<true>(sb, r0, lr, lm, SM_FH, SM_FL, SM_RH, SM_RL, racc);

    // ================= Phase 6: epilogue relu(em/sum + res) ================
    {
        float iA = ssum[r0 + grp];
        float iB = ssum[r0 + grp + 8];
        #pragma unroll
        for (int i = 0; i < 8; i++) {
            int c = h * A_ + (i << 3) + (qt << 1);
            float2 o;
            o.x = fmaxf(fmaf(eacc[i][0], iA, racc[i][0]), 0.f);
            o.y = fmaxf(fmaf(eacc[i][1], iA, racc[i][1]), 0.f);
            *(float2*)(out + ((size_t)(b * F_) + r0 + grp) * (H_ * A_) + c) = o;
            o.x = fmaxf(fmaf(eacc[i][2], iB, racc[i][2]), 0.f);
            o.y = fmaxf(fmaf(eacc[i][3], iB, racc[i][3]), 0.f);
            *(float2*)(out + ((size_t)(b * F_) + r0 + grp + 8) * (H_ * A_) + c) = o;
        }
    }
}

extern "C" void kernel_launch(void* const* d_in, const int* in_sizes, int n_in,
                              void* d_out, int out_size) {
    const float* feature = (const float*)d_in[0];
    const float* Qw      = (const float*)d_in[1];
    const float* Kw      = (const float*)d_in[2];
    const float* Vw      = (const float*)d_in[3];
    const float* res_w   = (const float*)d_in[4];
    float* out = (float*)d_out;

    cudaFuncSetAttribute(attn_mma_kernel,
                         cudaFuncAttributeMaxDynamicSharedMemorySize, SMEM_BYTES);
    attn_mma_kernel<<<B_ * H_, 256, SMEM_BYTES>>>(feature, Qw, Kw, Vw, res_w, out);
}

// round 10
// speedup vs baseline: 6.0639x; 1.2728x over previous
#include <cuda_runtime.h>
#include <cuda_bf16.h>
#include <cstdint>

// AttentionLayer: B=2048, F=128, E=64, H=4, A=64
//   out[b,f,h*64+a] = relu( softmax(q k^T) v + (feature @ res_w)[:, h*64:] )
//
// mma.sync bf16 hi/lo 3-term emulated fp32 on all five GEMMs.
// Register-resident dataflow: f, q, P live in registers as A-fragments
// (C-frag -> A-frag layout identity); only B operands (weights, k, v) go
// through SMEM. 1 CTA per (b,h), 256 threads, warp w owns rows [16w,16w+16).

#define B_ 2048
#define F_ 128
#define E_ 64
#define H_ 4
#define A_ 64

// ---------------- smem layout (bytes); bf16 tiles, row stride 144 B --------
#define SM_WQH 0        // weight tiles [64x64] row-major [e][a]
#define SM_WQL 9216
#define SM_WKH 18432
#define SM_WKL 27648
#define SM_WVH 36864
#define SM_WVL 46080
#define SM_RH  55296    // res_w slice [64x64]
#define SM_RL  64512
#define SM_KH  73728    // k [128x64] row-major [g][a]
#define SM_KL  92160
#define SM_VH  110592   // v [128x64] row-major [g][a]
#define SM_VL  129024
#define SMEM_BYTES 147456

// ---------------- PTX helpers ----------------------------------------------
__device__ __forceinline__ uint32_t smem_u32(const void* p) {
    uint32_t a;
    asm("{ .reg .u64 t; cvta.to.shared.u64 t, %1; cvt.u32.u64 %0, t; }"
        : "=r"(a) : "l"(p));
    return a;
}
__device__ __forceinline__ void ldsm4(uint32_t addr, uint32_t r[4]) {
    asm volatile("ldmatrix.sync.aligned.m8n8.x4.shared.b16 {%0,%1,%2,%3}, [%4];"
                 : "=r"(r[0]), "=r"(r[1]), "=r"(r[2]), "=r"(r[3]) : "r"(addr));
}
__device__ __forceinline__ void ldsm4t(uint32_t addr, uint32_t r[4]) {
    asm volatile("ldmatrix.sync.aligned.m8n8.x4.trans.shared.b16 {%0,%1,%2,%3}, [%4];"
                 : "=r"(r[0]), "=r"(r[1]), "=r"(r[2]), "=r"(r[3]) : "r"(addr));
}
__device__ __forceinline__ void mma16816(float d[4], const uint32_t a[4],
                                         uint32_t b0, uint32_t b1) {
    asm volatile(
        "mma.sync.aligned.m16n8k16.row.col.f32.bf16.bf16.f32 "
        "{%0,%1,%2,%3}, {%4,%5,%6,%7}, {%8,%9}, {%0,%1,%2,%3};"
        : "+f"(d[0]), "+f"(d[1]), "+f"(d[2]), "+f"(d[3])
        : "r"(a[0]), "r"(a[1]), "r"(a[2]), "r"(a[3]), "r"(b0), "r"(b1));
}
// 3-term hi/lo MMA pair for two adjacent 8-col accumulators
__device__ __forceinline__ void mma3(float dA[4], float dB[4],
                                     const uint32_t ah[4], const uint32_t al[4],
                                     const uint32_t bh[4], const uint32_t bl[4]) {
    mma16816(dA, ah, bh[0], bh[1]);
    mma16816(dB, ah, bh[2], bh[3]);
    mma16816(dA, ah, bl[0], bl[1]);
    mma16816(dB, ah, bl[2], bl[3]);
    mma16816(dA, al, bh[0], bh[1]);
    mma16816(dB, al, bh[2], bh[3]);
}

__device__ __forceinline__ uint32_t pack2(__nv_bfloat16 a, __nv_bfloat16 b) {
    return (uint32_t)__bfloat16_as_ushort(a) | ((uint32_t)__bfloat16_as_ushort(b) << 16);
}
__device__ __forceinline__ uint32_t pack_hilo(float a, float b, uint32_t& lo) {
    __nv_bfloat16 ha = __float2bfloat16_rn(a);
    __nv_bfloat16 hb = __float2bfloat16_rn(b);
    __nv_bfloat16 la = __float2bfloat16_rn(a - __bfloat162float(ha));
    __nv_bfloat16 lb = __float2bfloat16_rn(b - __bfloat162float(hb));
    lo = pack2(la, lb);
    return pack2(ha, hb);
}

__global__ __launch_bounds__(256, 1)
void attn_mma_kernel(const float* __restrict__ feature,
                     const float* __restrict__ Qw,
                     const float* __restrict__ Kw,
                     const float* __restrict__ Vw,
                     const float* __restrict__ res_w,
                     float* __restrict__ out) {
    extern __shared__ char smem[];
    const uint32_t sb = smem_u32(smem);
    const int t = threadIdx.x;
    const int w = t >> 5, l = t & 31;
    const int grp = l >> 2, qt = l & 3;      // C/A-fragment coords
    const int lr = l & 7, lm = l >> 3;       // ldmatrix lane coords
    const int b = blockIdx.x >> 2, h = blockIdx.x & 3;
    const int r0 = w * 16;                   // warp's output row base

    // ======== Phase 0a: f -> register A-fragments (hi/lo), loaded once =====
    uint32_t fh[4][4], fl[4][4];
    {
        const float* fb = feature + (size_t)b * (F_ * E_) + (size_t)r0 * E_;
        #pragma unroll
        for (int ks = 0; ks < 4; ks++) {
            float2 v0 = *(const float2*)(fb + grp * 64 + ks * 16 + qt * 2);
            float2 v1 = *(const float2*)(fb + (grp + 8) * 64 + ks * 16 + qt * 2);
            float2 v2 = *(const float2*)(fb + grp * 64 + ks * 16 + 8 + qt * 2);
            float2 v3 = *(const float2*)(fb + (grp + 8) * 64 + ks * 16 + 8 + qt * 2);
            fh[ks][0] = pack_hilo(v0.x, v0.y, fl[ks][0]);
            fh[ks][1] = pack_hilo(v1.x, v1.y, fl[ks][1]);
            fh[ks][2] = pack_hilo(v2.x, v2.y, fl[ks][2]);
            fh[ks][3] = pack_hilo(v3.x, v3.y, fl[ks][3]);
        }
    }

    // ======== Phase 0b: weights -> smem bf16 hi/lo (cooperative) ===========
    {
        const float* srcs[4] = {Qw + h * (E_ * A_), Kw + h * (E_ * A_),
                                Vw + h * (E_ * A_), res_w + h * A_};
        const int strd[4] = {A_, A_, A_, H_ * A_};
        const int dsth[4] = {SM_WQH, SM_WKH, SM_WVH, SM_RH};
        const int dstl[4] = {SM_WQL, SM_WKL, SM_WVL, SM_RL};
        #pragma unroll
        for (int p = 0; p < 4; p++) {
            const float* s = srcs[p];
            const int st = strd[p];
            #pragma unroll
            for (int it = 0; it < 4; it++) {
                int i = t + it * 256;
                int e = i >> 4, c4 = (i & 15) << 2;
                float4 v = *(const float4*)(s + e * st + c4);
                uint32_t lo0, lo1;
                uint32_t h0 = pack_hilo(v.x, v.y, lo0);
                uint32_t h1 = pack_hilo(v.z, v.w, lo1);
                uint32_t off = (uint32_t)(e * 144 + (c4 << 1));
                *(uint2*)(smem + dsth[p] + off) = make_uint2(h0, h1);
                *(uint2*)(smem + dstl[p] + off) = make_uint2(lo0, lo1);
            }
        }
    }
    __syncthreads();

    // GEMM with register A-frags (4 k-chunks), B from smem [K=64][N=64] (.trans)
    auto gemmA = [&](const uint32_t ah[4][4], const uint32_t al[4][4],
                     uint32_t bh_off, uint32_t bl_off, float acc[8][4]) {
        #pragma unroll
        for (int ks = 0; ks < 4; ks++) {
            #pragma unroll
            for (int p = 0; p < 4; p++) {
                uint32_t b_rel = (uint32_t)(((ks << 4) + lr + ((lm & 1) << 3)) * 144 +
                                            (p << 5) + ((lm >> 1) << 4));
                uint32_t bh[4], bl[4];
                ldsm4t(sb + bh_off + b_rel, bh);
                ldsm4t(sb + bl_off + b_rel, bl);
                mma3(acc[2 * p], acc[2 * p + 1], ah[ks], al[ks], bh, bl);
            }
        }
    };
    // C-frag -> A-frag conversion (hi/lo split), 4 k-chunks from 8 col-tiles
    auto to_frag4 = [&](const float acc[8][4], uint32_t oh[4][4], uint32_t ol[4][4]) {
        #pragma unroll
        for (int ks = 0; ks < 4; ks++) {
            oh[ks][0] = pack_hilo(acc[2 * ks][0],     acc[2 * ks][1],     ol[ks][0]);
            oh[ks][1] = pack_hilo(acc[2 * ks][2],     acc[2 * ks][3],     ol[ks][1]);
            oh[ks][2] = pack_hilo(acc[2 * ks + 1][0], acc[2 * ks + 1][1], ol[ks][2]);
            oh[ks][3] = pack_hilo(acc[2 * ks + 1][2], acc[2 * ks + 1][3], ol[ks][3]);
        }
    };
    // store C tile (16 rows x 64 cols) to smem as bf16 hi/lo, stride 144
    auto store_hilo = [&](const float acc[8][4], int oh, int ol) {
        #pragma unroll
        for (int i = 0; i < 8; i++) {
            int cbyte = (((i << 3) + (qt << 1)) << 1);
            uint32_t lo;
            uint32_t hi = pack_hilo(acc[i][0], acc[i][1], lo);
            *(uint32_t*)(smem + oh + (r0 + grp) * 144 + cbyte) = hi;
            *(uint32_t*)(smem + ol + (r0 + grp) * 144 + cbyte) = lo;
            hi = pack_hilo(acc[i][2], acc[i][3], lo);
            *(uint32_t*)(smem + oh + (r0 + grp + 8) * 144 + cbyte) = hi;
            *(uint32_t*)(smem + ol + (r0 + grp + 8) * 144 + cbyte) = lo;
        }
    };

    // ================= Phase 1: projections ================================
    uint32_t qh[4][4], ql[4][4];
    {
        float acc[8][4] = {};
        gemmA(fh, fl, SM_WQH, SM_WQL, acc);
        to_frag4(acc, qh, ql);               // q stays in registers
    }
    {
        float acc[8][4] = {};
        gemmA(fh, fl, SM_WKH, SM_WKL, acc);
        store_hilo(acc, SM_KH, SM_KL);       // k needed by all warps -> smem
    }
    {
        float acc[8][4] = {};
        gemmA(fh, fl, SM_WVH, SM_WVL, acc);
        store_hilo(acc, SM_VH, SM_VL);       // v needed by all warps -> smem
    }
    __syncthreads();

    // ================= Phase 2: S = q k^T (16 x 128 per warp) ==============
    float sacc[16][4] = {};
    #pragma unroll
    for (int ks = 0; ks < 4; ks++) {
        #pragma unroll
        for (int p = 0; p < 8; p++) {
            uint32_t b_rel = (uint32_t)(((p << 4) + lr + ((lm >> 1) << 3)) * 144 +
                                        (ks << 5) + ((lm & 1) << 4));
            uint32_t bh[4], bl[4];
            ldsm4(sb + SM_KH + b_rel, bh);
            ldsm4(sb + SM_KL + b_rel, bl);
            mma3(sacc[2 * p], sacc[2 * p + 1], qh[ks], ql[ks], bh, bl);
        }
    }

    // ================= Phase 3: softmax in registers =======================
    float invA, invB;
    {
        float mA = -3.402823466e38f, mB = -3.402823466e38f;
        #pragma unroll
        for (int i = 0; i < 16; i++) {
            mA = fmaxf(mA, fmaxf(sacc[i][0], sacc[i][1]));
            mB = fmaxf(mB, fmaxf(sacc[i][2], sacc[i][3]));
        }
        mA = fmaxf(mA, __shfl_xor_sync(0xFFFFFFFFu, mA, 1));
        mA = fmaxf(mA, __shfl_xor_sync(0xFFFFFFFFu, mA, 2));
        mB = fmaxf(mB, __shfl_xor_sync(0xFFFFFFFFu, mB, 1));
        mB = fmaxf(mB, __shfl_xor_sync(0xFFFFFFFFu, mB, 2));
        float sA = 0.f, sB = 0.f;
        #pragma unroll
        for (int i = 0; i < 16; i++) {
            sacc[i][0] = __expf(sacc[i][0] - mA);
            sacc[i][1] = __expf(sacc[i][1] - mA);
            sacc[i][2] = __expf(sacc[i][2] - mB);
            sacc[i][3] = __expf(sacc[i][3] - mB);
            sA += sacc[i][0] + sacc[i][1];
            sB += sacc[i][2] + sacc[i][3];
        }
        sA += __shfl_xor_sync(0xFFFFFFFFu, sA, 1);
        sA += __shfl_xor_sync(0xFFFFFFFFu, sA, 2);
        sB += __shfl_xor_sync(0xFFFFFFFFu, sB, 1);
        sB += __shfl_xor_sync(0xFFFFFFFFu, sB, 2);
        invA = 1.0f / sA;
        invB = 1.0f / sB;
    }

    // P (unnormalized) -> register A-fragments, 8 k-chunks
    uint32_t ph[8][4], pl[8][4];
    #pragma unroll
    for (int ks = 0; ks < 8; ks++) {
        ph[ks][0] = pack_hilo(sacc[2 * ks][0],     sacc[2 * ks][1],     pl[ks][0]);
        ph[ks][1] = pack_hilo(sacc[2 * ks][2],     sacc[2 * ks][3],     pl[ks][1]);
        ph[ks][2] = pack_hilo(sacc[2 * ks + 1][0], sacc[2 * ks + 1][1], pl[ks][2]);
        ph[ks][3] = pack_hilo(sacc[2 * ks + 1][2], sacc[2 * ks + 1][3], pl[ks][3]);
    }

    // ================= Phase 4: em = P @ v  (K=128) ========================
    float eacc[8][4] = {};
    #pragma unroll
    for (int ks = 0; ks < 8; ks++) {
        #pragma unroll
        for (int p = 0; p < 4; p++) {
            uint32_t b_rel = (uint32_t)(((ks << 4) + lr + ((lm & 1) << 3)) * 144 +
                                        (p << 5) + ((lm >> 1) << 4));
            uint32_t bh[4], bl[4];
            ldsm4t(sb + SM_VH + b_rel, bh);
            ldsm4t(sb + SM_VL + b_rel, bl);
            mma3(eacc[2 * p], eacc[2 * p + 1], ph[ks], pl[ks], bh, bl);
        }
    }

    // ================= Phase 5: res = f @ res_w slice ======================
    float racc[8][4] = {};
    gemmA(fh, fl, SM_RH, SM_RL, racc);

    // ================= Phase 6: epilogue relu(em/sum + res) ================
    {
        #pragma unroll
        for (int i = 0; i < 8; i++) {
            int c = h * A_ + (i << 3) + (qt << 1);
            float2 o;
            o.x = fmaxf(fmaf(eacc[i][0], invA, racc[i][0]), 0.f);
            o.y = fmaxf(fmaf(eacc[i][1], invA, racc[i][1]), 0.f);
            *(float2*)(out + ((size_t)(b * F_) + r0 + grp) * (H_ * A_) + c) = o;
            o.x = fmaxf(fmaf(eacc[i][2], invB, racc[i][2]), 0.f);
            o.y = fmaxf(fmaf(eacc[i][3], invB, racc[i][3]), 0.f);
            *(float2*)(out + ((size_t)(b * F_) + r0 + grp + 8) * (H_ * A_) + c) = o;
        }
    }
}

extern "C" void kernel_launch(void* const* d_in, const int* in_sizes, int n_in,
                              void* d_out, int out_size) {
    const float* feature = (const float*)d_in[0];
    const float* Qw      = (const float*)d_in[1];
    const float* Kw      = (const float*)d_in[2];
    const float* Vw      = (const float*)d_in[3];
    const float* res_w   = (const float*)d_in[4];
    float* out = (float*)d_out;

    cudaFuncSetAttribute(attn_mma_kernel,
                         cudaFuncAttributeMaxDynamicSharedMemorySize, SMEM_BYTES);
    attn_mma_kernel<<<B_ * H_, 256, SMEM_BYTES>>>(feature, Qw, Kw, Vw, res_w, out);
}